// round 13
// baseline (speedup 1.0000x reference)
#include <cuda_runtime.h>
#include <cuda_fp16.h>
#include <math.h>
#include <stdint.h>

#define BATCH 2
#define CH    32
#define VOL   (96*96*96)
#define NRR   100
#define RHN   256
#define REN   128
#define INV_V (1.0f/884736.0f)
#define EPSN  1e-5f
#define PXD 132
#define PYD 98
#define PZD 98
#define PVOX (PZD*PYD*PXD)
#define BSTRIDE 104
#define BTILE   (32*BSTRIDE)

typedef unsigned long long ull;

// ---------------- f32x2 helpers ----------------
__device__ __forceinline__ void fma2(ull& d, ull a, ull b) {
    asm("fma.rn.f32x2 %0, %1, %2, %3;" : "=l"(d) : "l"(a), "l"(b), "l"(d));
}
__device__ __forceinline__ ull pack2f(float v) {
    ull r; asm("mov.b64 %0, {%1, %1};" : "=l"(r) : "f"(v)); return r;
}
__device__ __forceinline__ void unpack2f(float& lo, float& hi, ull a) {
    asm("mov.b64 {%0, %1}, %2;" : "=f"(lo), "=f"(hi) : "l"(a));
}

// ---------------- warp MMA helpers (fp16) ----------------
__device__ __forceinline__ uint32_t smem_u32(const void* p) {
    uint32_t a;
    asm("{ .reg .u64 t; cvta.to.shared.u64 t, %1; cvt.u32.u64 %0, t; }" : "=r"(a) : "l"(p));
    return a;
}
#define LDSM_X4(r0,r1,r2,r3,addr) \
    asm volatile("ldmatrix.sync.aligned.m8n8.x4.shared.b16 {%0,%1,%2,%3}, [%4];" \
        : "=r"(r0),"=r"(r1),"=r"(r2),"=r"(r3) : "r"(addr))
#define LDSM_X4_T(r0,r1,r2,r3,addr) \
    asm volatile("ldmatrix.sync.aligned.m8n8.x4.trans.shared.b16 {%0,%1,%2,%3}, [%4];" \
        : "=r"(r0),"=r"(r1),"=r"(r2),"=r"(r3) : "r"(addr))
#define MMA16816(d, a0,a1,a2,a3, b0,b1) \
    asm volatile("mma.sync.aligned.m16n8k16.row.col.f32.f16.f16.f32 " \
        "{%0,%1,%2,%3}, {%4,%5,%6,%7}, {%8,%9}, {%0,%1,%2,%3};" \
        : "+f"((d)[0]),"+f"((d)[1]),"+f"((d)[2]),"+f"((d)[3]) \
        : "r"(a0),"r"(a1),"r"(a2),"r"(a3), "r"(b0),"r"(b1))

__device__ __forceinline__ uint32_t packh2(float a, float b) {
    __half2 h = __floats2half2_rn(a, b);
    return *(uint32_t*)&h;
}
__device__ __forceinline__ float2 unph2(uint32_t u) {
    return __half22float2(*(__half2*)&u);
}

// ---------------- scratch ----------------
__device__ __half g_raw[(size_t)BATCH*VOL*CH];               // channels-last conv out (fp16)
__device__ __half g_pad[(size_t)BATCH*PVOX*CH];              // borders stay zero forever
__device__ __align__(16) __half g_wprep[3*9*2*BTILE];        // [L][dzdy][h/l]
__device__ float g_ssum[4][BATCH*CH][2];
__device__ float g_roi [BATCH*NRR*CH];
__device__ float g_msum[NRR];

__global__ void init_kernel() {
    int t = threadIdx.x;
    float* ss = &g_ssum[0][0][0];
    for (int i = t; i < 4*BATCH*CH*2; i += 256) ss[i] = 0.f;
    for (int i = t; i < BATCH*NRR*CH; i += 256) g_roi[i] = 0.f;
    for (int i = t; i < NRR; i += 256) g_msum[i] = 0.f;
}

// ---------------- weight prep: fp16 hi/lo tiles ----------------
__global__ void wprep_kernel(const float* __restrict__ convk_w) {
    const int L = blockIdx.x / 9;
    const int r = blockIdx.x % 9;
    const int dz = r / 3, dy = r % 3;
    __half* bh = g_wprep + ((size_t)(L*9 + r)*2 + 0)*BTILE;
    __half* bl = bh + BTILE;
    for (int i = threadIdx.x; i < 32*BSTRIDE; i += 256) {
        int co = i / BSTRIDE, k = i % BSTRIDE;
        float wv = 0.f;
        if (k < 96) {
            int dx = k >> 5, ci = k & 31;
            wv = convk_w[(size_t)((L*32 + co)*32 + ci)*27 + (dz*3 + dy)*3 + dx];
        }
        __half h = __float2half(wv);
        bh[i] = h;
        bl[i] = __float2half(wv - __half2float(h));
    }
}

// ---------------- conv0: 1->32 direct (f32x2) + fused stats ----------------
__global__ void conv0_kernel(const float* __restrict__ data,
                             const float* __restrict__ w0,
                             __half* __restrict__ raw,
                             float* __restrict__ ss) {
    __shared__ __align__(16) float ws[27*32];
    __shared__ float s_sm[32], q_sm[32];
    const int tid = threadIdx.x;
    for (int i = tid; i < 864; i += 256) {
        int tap = i / 32, c = i % 32;
        ws[tap*32 + c] = w0[c*27 + tap];
    }
    if (tid < 32) { s_sm[tid] = 0.f; q_sm[tid] = 0.f; }
    __syncthreads();
    const int v = blockIdx.x*256 + tid;
    const int b = v / VOL, s = v % VOL;
    const int z = s / 9216, y = (s / 96) % 96, x = s % 96;
    const float* p = data + (size_t)b * VOL;

    ull acc[16];
    #pragma unroll
    for (int q = 0; q < 16; q++) acc[q] = 0ULL;
    #pragma unroll
    for (int dz = 0; dz < 3; dz++) {
        int zz = z + dz - 1; if ((unsigned)zz >= 96u) continue;
        #pragma unroll
        for (int dy = 0; dy < 3; dy++) {
            int yy = y + dy - 1; if ((unsigned)yy >= 96u) continue;
            #pragma unroll
            for (int dx = 0; dx < 3; dx++) {
                int xx = x + dx - 1; if ((unsigned)xx >= 96u) continue;
                ull val = pack2f(__ldg(p + ((size_t)zz*96 + yy)*96 + xx));
                const ulonglong2* wp = (const ulonglong2*)(ws + ((dz*3+dy)*3+dx)*32);
                #pragma unroll
                for (int q = 0; q < 8; q++) {
                    ulonglong2 ww = wp[q];
                    fma2(acc[q*2+0], val, ww.x);
                    fma2(acc[q*2+1], val, ww.y);
                }
            }
        }
    }
    float af[32];
    #pragma unroll
    for (int q = 0; q < 16; q++) unpack2f(af[q*2], af[q*2+1], acc[q]);

    uint4* o = (uint4*)(raw + (size_t)v * 32);
    #pragma unroll
    for (int q = 0; q < 4; q++)
        o[q] = make_uint4(packh2(af[q*8+0], af[q*8+1]), packh2(af[q*8+2], af[q*8+3]),
                          packh2(af[q*8+4], af[q*8+5]), packh2(af[q*8+6], af[q*8+7]));

    // fused per-channel stats (warp tree-reduce, then smem atomics)
    float sq[32];
    #pragma unroll
    for (int c = 0; c < 32; c++) sq[c] = af[c]*af[c];
    #pragma unroll
    for (int off = 16; off; off >>= 1) {
        #pragma unroll
        for (int c = 0; c < 32; c++) {
            af[c] += __shfl_down_sync(0xffffffffu, af[c], off);
            sq[c] += __shfl_down_sync(0xffffffffu, sq[c], off);
        }
    }
    if ((tid & 31) == 0) {
        #pragma unroll
        for (int c = 0; c < 32; c++) {
            atomicAdd(&s_sm[c], af[c]);
            atomicAdd(&q_sm[c], sq[c]);
        }
    }
    __syncthreads();
    if (tid < 32) {
        atomicAdd(&ss[(b*32 + tid)*2 + 0], s_sm[tid]);
        atomicAdd(&ss[(b*32 + tid)*2 + 1], q_sm[tid]);
    }
}

// ---------------- normalize + relu (fp16 raw -> fp16 padded) ----------------
__global__ void norm_split_kernel(const __half* __restrict__ raw, const float* __restrict__ ss,
                                  __half* __restrict__ pad) {
    __shared__ float na_s[64], nb_s[64];
    if (threadIdx.x < 64) {
        float s = ss[threadIdx.x*2], q = ss[threadIdx.x*2+1];
        float mm = s * INV_V;
        float var = fmaxf(q * INV_V - mm*mm, 0.f);
        float rstd = rsqrtf(var + EPSN);
        na_s[threadIdx.x] = rstd; nb_s[threadIdx.x] = -mm * rstd;
    }
    __syncthreads();
    int v = blockIdx.x*256 + threadIdx.x;
    int b = v / VOL, sidx = v % VOL;
    int z = sidx / 9216, y = (sidx / 96) % 96, x = sidx % 96;
    size_t pv = (((size_t)(b*PZD + z + 1))*PYD + (y + 1))*PXD + (x + 1);

    const uint4* rp = (const uint4*)(raw + (size_t)v * 32);
    const float* na = na_s + b*32;
    const float* nb = nb_s + b*32;
    uint4* oh = (uint4*)(pad + pv*32);
    #pragma unroll
    for (int q = 0; q < 4; q++) {
        uint4 f = rp[q];
        uint32_t w[4];
        uint32_t in[4] = { f.x, f.y, f.z, f.w };
        #pragma unroll
        for (int j = 0; j < 4; j++) {
            float2 vv = unph2(in[j]);
            int c = q*8 + j*2;
            float v0 = fmaxf(fmaf(vv.x, na[c],   nb[c]),   0.f);
            float v1 = fmaxf(fmaf(vv.y, na[c+1], nb[c+1]), 0.f);
            w[j] = packh2(v0, v1);
        }
        oh[q] = make_uint4(w[0], w[1], w[2], w[3]);
    }
}

// ---------------- warp-MMA conv 32->32 + fused stats (fp16, 2 passes) ----------------
__global__ void __launch_bounds__(768, 1)
conv_mma_kernel(const __half* __restrict__ pad,
                const __half* __restrict__ wp,
                __half* __restrict__ raw,
                float* __restrict__ ss)
{
    extern __shared__ __half bsm[];
    __shared__ float s_sm[64], q_sm[64];
    const int tid = threadIdx.x;
    {
        const uint4* s = (const uint4*)wp;
        uint4* d = (uint4*)bsm;
        for (int i = tid; i < 18*BTILE/8; i += 768) d[i] = s[i];
    }
    if (tid < 64) { s_sm[tid] = 0.f; q_sm[tid] = 0.f; }
    __syncthreads();

    const uint32_t bbase0 = smem_u32(bsm);
    const int lane = tid & 31;
    const int warp = tid >> 5;
    const int rowsel = warp / 3;          // 0..7
    const int x0 = (warp % 3) * 32;
    const int tg  = lane & 3;
    const int gid = lane >> 2;
    const int bg = lane >> 3;
    const int b_n  = ((bg >> 1) << 3) + (lane & 7);
    const int b_kh = bg & 1;

    for (int t = blockIdx.x; t < BATCH*96*12; t += gridDim.x) {
        const int b  = t / (96*12);
        const int rm = t % (96*12);
        const int z  = rm / 12;
        const int y  = (rm % 12)*8 + rowsel;

        float dacc[2][4][4];
        #pragma unroll
        for (int st = 0; st < 2; st++)
            #pragma unroll
            for (int nt = 0; nt < 4; nt++)
                #pragma unroll
                for (int j = 0; j < 4; j++) dacc[st][nt][j] = 0.f;

        #pragma unroll 1
        for (int r = 0; r < 9; r++) {
            const int dz = r / 3, dy = r % 3;
            const size_t rowb = (((size_t)(b*PZD + z + dz))*PYD + (y + dy))*PXD;
            const uint32_t bb_h = bbase0 + (uint32_t)(r*2 + 0)*(BTILE*2);
            const uint32_t bb_l = bbase0 + (uint32_t)(r*2 + 1)*(BTILE*2);

            #pragma unroll
            for (int kc = 0; kc < 6; kc++) {
                const int dx = kc >> 1;
                const int j0 = (kc & 1)*16;

                const uint32_t ko = (uint32_t)(kc*32 + b_kh*16);
                const uint32_t ro = (uint32_t)b_n * (BSTRIDE*2) + ko;
                uint32_t bh[8], bl[8];
                LDSM_X4(bh[0],bh[1],bh[2],bh[3], bb_h + ro);
                LDSM_X4(bh[4],bh[5],bh[6],bh[7], bb_h + ro + 16u*(BSTRIDE*2));
                LDSM_X4(bl[0],bl[1],bl[2],bl[3], bb_l + ro);
                LDSM_X4(bl[4],bl[5],bl[6],bl[7], bb_l + ro + 16u*(BSTRIDE*2));

                #pragma unroll
                for (int st = 0; st < 2; st++) {
                    const size_t ab = (rowb + (size_t)(x0 + st*16 + gid + dx))*32 + j0 + tg*2;
                    uint32_t ah0 = *(const uint32_t*)(pad + ab);
                    uint32_t ah1 = *(const uint32_t*)(pad + ab + 256);
                    uint32_t ah2 = *(const uint32_t*)(pad + ab + 8);
                    uint32_t ah3 = *(const uint32_t*)(pad + ab + 264);
                    #pragma unroll
                    for (int nt = 0; nt < 4; nt++) {
                        MMA16816(dacc[st][nt], ah0,ah1,ah2,ah3, bh[nt*2], bh[nt*2+1]);
                        MMA16816(dacc[st][nt], ah0,ah1,ah2,ah3, bl[nt*2], bl[nt*2+1]);
                    }
                }
            }
        }

        #pragma unroll
        for (int st = 0; st < 2; st++) {
            __half* orow = raw + ((size_t)b*VOL + (size_t)z*9216 + (size_t)y*96 + x0 + st*16)*32;
            #pragma unroll
            for (int nt = 0; nt < 4; nt++) {
                const int col = nt*8 + tg*2;
                *(uint32_t*)(orow + (size_t)gid*32 + col)     = packh2(dacc[st][nt][0], dacc[st][nt][1]);
                *(uint32_t*)(orow + (size_t)(gid+8)*32 + col) = packh2(dacc[st][nt][2], dacc[st][nt][3]);
            }
        }

        float sv[8], qv[8];
        #pragma unroll
        for (int nt = 0; nt < 4; nt++) {
            sv[nt*2+0] = (dacc[0][nt][0] + dacc[0][nt][2]) + (dacc[1][nt][0] + dacc[1][nt][2]);
            sv[nt*2+1] = (dacc[0][nt][1] + dacc[0][nt][3]) + (dacc[1][nt][1] + dacc[1][nt][3]);
            float q0 = fmaf(dacc[0][nt][0], dacc[0][nt][0], dacc[0][nt][2]*dacc[0][nt][2]);
            float q1 = fmaf(dacc[0][nt][1], dacc[0][nt][1], dacc[0][nt][3]*dacc[0][nt][3]);
            qv[nt*2+0] = fmaf(dacc[1][nt][0], dacc[1][nt][0], fmaf(dacc[1][nt][2], dacc[1][nt][2], q0));
            qv[nt*2+1] = fmaf(dacc[1][nt][1], dacc[1][nt][1], fmaf(dacc[1][nt][3], dacc[1][nt][3], q1));
        }
        #pragma unroll
        for (int o = 4; o < 32; o <<= 1) {
            #pragma unroll
            for (int j = 0; j < 8; j++) {
                sv[j] += __shfl_xor_sync(0xffffffffu, sv[j], o);
                qv[j] += __shfl_xor_sync(0xffffffffu, qv[j], o);
            }
        }
        if (gid == 0) {
            #pragma unroll
            for (int nt = 0; nt < 4; nt++) {
                int c = b*32 + nt*8 + tg*2;
                atomicAdd(&s_sm[c],   sv[nt*2+0]);
                atomicAdd(&s_sm[c+1], sv[nt*2+1]);
                atomicAdd(&q_sm[c],   qv[nt*2+0]);
                atomicAdd(&q_sm[c+1], qv[nt*2+1]);
            }
        }
    }
    __syncthreads();
    if (tid < 64) {
        atomicAdd(&ss[tid*2 + 0], s_sm[tid]);
        atomicAdd(&ss[tid*2 + 1], q_sm[tid]);
    }
}

// ---------------- pool: warp-MMA GEMM over raw (inline norm), 96-voxel rows ----------------
#define ASTR 104
__global__ void __launch_bounds__(256, 2)
pool_kernel(const __half* __restrict__ raw, const float* __restrict__ ss,
            const float* __restrict__ mask)
{
    __shared__ __half a_sm[128*ASTR];          // mask rows [128][96used]
    __shared__ __half e_sm[2*96*40];           // [bb][v][c] stride 40
    __shared__ float na_s[64], nb_s[64];

    const int tid  = threadIdx.x;
    const int lane = tid & 31;
    const int warp = tid >> 5;
    const int m0   = warp * 16;

    if (tid < 64) {
        float s = ss[tid*2], q = ss[tid*2+1];
        float mm = s * INV_V;
        float var = fmaxf(q * INV_V - mm*mm, 0.f);
        float rstd = rsqrtf(var + EPSN);
        na_s[tid] = rstd; nb_s[tid] = -mm * rstd;
    }
    for (int i = tid; i < 28*ASTR; i += 256)
        a_sm[100*ASTR + i] = __float2half(0.f);

    float acc[8][4];
    #pragma unroll
    for (int j = 0; j < 8; j++)
        #pragma unroll
        for (int q = 0; q < 4; q++) acc[j][q] = 0.f;
    float msl[10];
    #pragma unroll
    for (int k = 0; k < 10; k++) msl[k] = 0.f;

    const uint32_t abase = smem_u32(a_sm);
    const uint32_t ebase = smem_u32(e_sm);
    const int nch = VOL / 96;                  // 9216 rows
    __syncthreads();

    for (int chn = blockIdx.x; chn < nch; chn += gridDim.x) {
        const int v0 = chn * 96;
        __syncthreads();

        // mask rows -> fp16 smem (+ per-(thread,k) row-sum accumulators)
        {
            int k = 0;
            for (int u = tid; u < 2400; u += 256, k++) {
                const int r = u / 24, vq = u % 24;
                float4 f = *(const float4*)(mask + (size_t)r*VOL + v0 + vq*4);
                msl[k] += (f.x + f.y) + (f.z + f.w);
                uint32_t p0 = packh2(f.x, f.y);
                uint32_t p1 = packh2(f.z, f.w);
                asm volatile("st.shared.v2.b32 [%0], {%1, %2};"
                    :: "r"(abase + (uint32_t)(r*(ASTR*2) + vq*8)), "r"(p0), "r"(p1) : "memory");
            }
        }

        // e tiles from raw with inline norm: 2 bb x 96 v x 4 cq = 768 uint4
        #pragma unroll
        for (int ii = 0; ii < 3; ii++) {
            const int i = tid + ii*256;
            const int bb  = i / 384;
            const int rem = i % 384;
            const int v   = rem >> 2;
            const int cq  = rem & 3;
            uint4 f = *(const uint4*)(raw + ((size_t)bb*VOL + v0 + v)*32 + cq*8);
            uint32_t in[4] = { f.x, f.y, f.z, f.w };
            uint32_t w[4];
            #pragma unroll
            for (int j = 0; j < 4; j++) {
                float2 vv = unph2(in[j]);
                int c = bb*32 + cq*8 + j*2;
                float v0f = fmaxf(fmaf(vv.x, na_s[c],   nb_s[c]),   0.f);
                float v1f = fmaxf(fmaf(vv.y, na_s[c+1], nb_s[c+1]), 0.f);
                w[j] = packh2(v0f, v1f);
            }
            *(uint4*)((char*)e_sm + (size_t)(bb*96 + v)*80 + cq*16) = make_uint4(w[0], w[1], w[2], w[3]);
        }
        __syncthreads();

        #pragma unroll
        for (int ks = 0; ks < 6; ks++) {
            uint32_t a0, a1, a2, a3;
            LDSM_X4(a0, a1, a2, a3,
                abase + (uint32_t)((m0 + (lane & 15))*(ASTR*2) + ks*32 + (lane >> 4)*16));
            #pragma unroll
            for (int bb = 0; bb < 2; bb++) {
                const uint32_t eb = ebase + (uint32_t)((bb*96 + ks*16)*80)
                                 + (uint32_t)((lane & 15)*80 + (lane >> 4)*16);
                uint32_t b0,b1,b2,b3, c0,c1,c2,c3;
                LDSM_X4_T(b0, b1, b2, b3, eb);
                LDSM_X4_T(c0, c1, c2, c3, eb + 32);
                const int j0 = bb*4;
                MMA16816(acc[j0+0], a0,a1,a2,a3, b0,b1);
                MMA16816(acc[j0+1], a0,a1,a2,a3, b2,b3);
                MMA16816(acc[j0+2], a0,a1,a2,a3, c0,c1);
                MMA16816(acc[j0+3], a0,a1,a2,a3, c2,c3);
            }
        }
    }

    const int rlo = m0 + (lane >> 2);
    const int cc  = (lane & 3) * 2;
    #pragma unroll
    for (int j = 0; j < 8; j++) {
        const int bb = j >> 2, q = j & 3;
        const int c = q*8 + cc;
        if (rlo < NRR) {
            atomicAdd(&g_roi[(bb*NRR + rlo)*CH + c    ], acc[j][0]);
            atomicAdd(&g_roi[(bb*NRR + rlo)*CH + c + 1], acc[j][1]);
        }
        if (rlo + 8 < NRR) {
            atomicAdd(&g_roi[(bb*NRR + rlo + 8)*CH + c    ], acc[j][2]);
            atomicAdd(&g_roi[(bb*NRR + rlo + 8)*CH + c + 1], acc[j][3]);
        }
    }
    {
        int k = 0;
        for (int u = tid; u < 2400; u += 256, k++) {
            const int r = u / 24;
            atomicAdd(&g_msum[r], msl[k]);
        }
    }
}

// ---------------- per-ROI MLPs ----------------
__global__ void mlp_kernel(const float* __restrict__ sw1, const float* __restrict__ sb1,
                           const float* __restrict__ sw2, const float* __restrict__ sb2,
                           const float* __restrict__ pw1, const float* __restrict__ pb1,
                           const float* __restrict__ pw2, const float* __restrict__ pb2,
                           float* __restrict__ out)
{
    const int b = blockIdx.x / NRR;
    const int r = blockIdx.x % NRR;
    const int tid = threadIdx.x;
    __shared__ float roi_s[32], h_s[64], sf_s[32], h2_s[256];

    if (tid < 32)
        roi_s[tid] = g_roi[(b*NRR + r)*CH + tid] / g_msum[r];
    __syncthreads();
    if (tid < 64) {
        float s = sb1[r*64 + tid];
        #pragma unroll
        for (int c = 0; c < 32; c++)
            s = fmaf(roi_s[c], sw1[(r*CH + c)*64 + tid], s);
        h_s[tid] = fmaxf(s, 0.f);
    }
    __syncthreads();
    if (tid < 32) {
        float s = sb2[r*CH + tid];
        #pragma unroll
        for (int j = 0; j < 64; j++)
            s = fmaf(h_s[j], sw2[(r*64 + j)*CH + tid], s);
        sf_s[tid] = roi_s[tid] / (1.f + expf(-s));
    }
    __syncthreads();
    {
        float s = pb1[r*RHN + tid];
        #pragma unroll
        for (int c = 0; c < 32; c++)
            s = fmaf(sf_s[c], pw1[(r*CH + c)*RHN + tid], s);
        h2_s[tid] = fmaxf(s, 0.f);
    }
    __syncthreads();
    if (tid < 128) {
        float s = pb2[r*REN + tid];
        for (int k = 0; k < 256; k++)
            s = fmaf(h2_s[k], pw2[(r*RHN + k)*REN + tid], s);
        out[(b*NRR + r)*REN + tid] = s;
    }
}

// ---------------- launch ----------------
extern "C" void kernel_launch(void* const* d_in, const int* in_sizes, int n_in,
                              void* d_out, int out_size)
{
    const float* data    = (const float*)d_in[0];
    const float* mask    = (const float*)d_in[1];
    const float* conv0_w = (const float*)d_in[2];
    const float* convk_w = (const float*)d_in[4];
    const float* sw1 = (const float*)d_in[6];
    const float* sb1 = (const float*)d_in[7];
    const float* sw2 = (const float*)d_in[8];
    const float* sb2 = (const float*)d_in[9];
    const float* pw1 = (const float*)d_in[10];
    const float* pb1 = (const float*)d_in[11];
    const float* pw2 = (const float*)d_in[12];
    const float* pb2 = (const float*)d_in[13];
    float* out = (float*)d_out;

    __half* raw = nullptr; cudaGetSymbolAddress((void**)&raw, g_raw);
    __half* pad = nullptr; cudaGetSymbolAddress((void**)&pad, g_pad);
    __half* wpre = nullptr; cudaGetSymbolAddress((void**)&wpre, g_wprep);
    float* ssum = nullptr; cudaGetSymbolAddress((void**)&ssum, g_ssum);
    float* ss0 = ssum + 0*BATCH*CH*2;
    float* ss1 = ssum + 1*BATCH*CH*2;
    float* ss2 = ssum + 2*BATCH*CH*2;
    float* ss3 = ssum + 3*BATCH*CH*2;

    const int SMEMB = 18*BTILE*2;
    cudaFuncSetAttribute(conv_mma_kernel, cudaFuncAttributeMaxDynamicSharedMemorySize, SMEMB);

    const int nnb = BATCH*VOL/256;
    const size_t LW = (size_t)9*2*BTILE;

    init_kernel<<<1, 256>>>();
    wprep_kernel<<<27, 256>>>(convk_w);

    conv0_kernel<<<nnb, 256>>>(data, conv0_w, raw, ss0);
    norm_split_kernel<<<nnb, 256>>>(raw, ss0, pad);

    conv_mma_kernel<<<148, 768, SMEMB>>>(pad, wpre + 0*LW, raw, ss1);
    norm_split_kernel<<<nnb, 256>>>(raw, ss1, pad);

    conv_mma_kernel<<<148, 768, SMEMB>>>(pad, wpre + 1*LW, raw, ss2);
    norm_split_kernel<<<nnb, 256>>>(raw, ss2, pad);

    conv_mma_kernel<<<148, 768, SMEMB>>>(pad, wpre + 2*LW, raw, ss3);

    pool_kernel<<<296, 256>>>(raw, ss3, mask);
    mlp_kernel<<<BATCH*NRR, 256>>>(sw1, sb1, sw2, sb2, pw1, pb1, pw2, pb2, out);
}